// round 15
// baseline (speedup 1.0000x reference)
#include <cuda_runtime.h>
#include <cuda_fp16.h>
#include <cstdint>

// ===========================================================================
// GaussProjDrop R15: R14 + out_g stored fp16.
//   out_g = (xg @ U)/3 + xg  (computed in GEMM epilogue, fp16 store)
//   final kernel: pure permutation out[r][a(i)] = float(out_g[r][i])
// Traffic: permute 128->96 MB, GEMM epilogue writes 64->32 MB.
// ===========================================================================

namespace {
constexpr int M = 8 * 2048;   // 16384
constexpr int C = 1024;
constexpr float RAND_SCALE = 1.0f / 3.0f;

constexpr int BM = 128, BN = 128, BK = 64;
constexpr int NKT = C / BK;                  // 16
constexpr int STAGES = 3;
constexpr int A_SM_BYTES = BM * BK * 2;      // 16384
constexpr int B_SM_BYTES = BK * BN * 2;      // 16384
constexpr int STAGE_BYTES = A_SM_BYTES + B_SM_BYTES;   // 32768
constexpr int GSMEM = STAGES * STAGE_BYTES;            // 98304 -> 2 CTA/SM

constexpr int GATHER_BLOCKS = M / 8;                // 2048 (8 rows, 512 thr)
constexpr int UCONV_BLOCKS  = (C * C) / (512 * 4);  // 512
}

// Scratch (__device__ globals: allocation-free rule)
__device__ __half g_xg[(size_t)M * C];   // gathered x, fp16    (32 MB)
__device__ __half g_uh[(size_t)C * C];   // U, fp16               (2 MB)
__device__ __half g_og[(size_t)M * C];   // out_g fp16           (32 MB)

// ---------------------------------------------------------------------------
__device__ __forceinline__ void cp_async16(uint32_t dst, const void* src) {
    asm volatile("cp.async.cg.shared.global [%0], [%1], 16;" :: "r"(dst), "l"(src));
}
__device__ __forceinline__ uint32_t smem_u32(const void* p) {
    uint32_t a;
    asm("{ .reg .u64 t; cvta.to.shared.u64 t, %1; cvt.u32.u64 %0, t; }" : "=r"(a) : "l"(p));
    return a;
}
__device__ __forceinline__ void ldsm_x4(uint32_t r[4], uint32_t addr) {
    asm volatile("ldmatrix.sync.aligned.m8n8.x4.shared.b16 {%0,%1,%2,%3}, [%4];"
                 : "=r"(r[0]), "=r"(r[1]), "=r"(r[2]), "=r"(r[3]) : "r"(addr));
}
__device__ __forceinline__ void ldsm_x4_t(uint32_t r[4], uint32_t addr) {
    asm volatile("ldmatrix.sync.aligned.m8n8.x4.trans.shared.b16 {%0,%1,%2,%3}, [%4];"
                 : "=r"(r[0]), "=r"(r[1]), "=r"(r[2]), "=r"(r[3]) : "r"(addr));
}
__device__ __forceinline__ void mma_f16(float c[4], const uint32_t a[4], uint32_t b0, uint32_t b1) {
    asm volatile(
        "mma.sync.aligned.m16n8k16.row.col.f32.f16.f16.f32 "
        "{%0,%1,%2,%3}, {%4,%5,%6,%7}, {%8,%9}, {%0,%1,%2,%3};"
        : "+f"(c[0]), "+f"(c[1]), "+f"(c[2]), "+f"(c[3])
        : "r"(a[0]), "r"(a[1]), "r"(a[2]), "r"(a[3]), "r"(b0), "r"(b1));
}

// ---------------------------------------------------------------------------
// Launch 1 (merged): gather (512 thr, 8 rows, 2-stage cp.async) + uconv.
// ---------------------------------------------------------------------------
__global__ void __launch_bounds__(512)
gather_uconv_kernel(const float* __restrict__ x,
                    const float* __restrict__ U,
                    const int*   __restrict__ perm,
                    const int*   __restrict__ randint) {
    const int tid = threadIdx.x;

    if (blockIdx.x >= GATHER_BLOCKS) {
        int i = ((blockIdx.x - GATHER_BLOCKS) * 512 + tid) * 4;
        float4 v = *reinterpret_cast<const float4*>(U + i);
        *reinterpret_cast<__half2*>(g_uh + i)     = __floats2half2_rn(v.x, v.y);
        *reinterpret_cast<__half2*>(g_uh + i + 2) = __floats2half2_rn(v.z, v.w);
        return;
    }

    __shared__ float sx[8][C];                // 32 KB, two 4-row stages
    const int r0 = blockIdx.x * 8;
    const unsigned mult = ((unsigned)randint[0] * 6u) & 1023u;
    const uint32_t sxb = smem_u32(sx);

    #pragma unroll
    for (int s = 0; s < 2; s++) {
        #pragma unroll
        for (int i = 0; i < 2; i++) {
            int id = tid + i * 512;
            int rr = id >> 8, c4 = (id & 255) * 4;
            int row = s * 4 + rr;
            cp_async16(sxb + (row * C + c4) * 4,
                       x + (size_t)(r0 + row) * C + c4);
        }
        asm volatile("cp.async.commit_group;" ::: "memory");
    }

    asm volatile("cp.async.wait_group 1;" ::: "memory");
    __syncthreads();
    #pragma unroll
    for (int i = 0; i < 4; i++) {
        int id = tid + i * 512;
        int rr = id >> 9, j = (id & 511) * 2;
        unsigned m = (mult * (unsigned)(r0 + rr) + 1u) & 1023u;
        unsigned a0 = ((unsigned)perm[j]     * m) & 1023u;
        unsigned a1 = ((unsigned)perm[j + 1] * m) & 1023u;
        __half2 h = __floats2half2_rn(sx[rr][a0], sx[rr][a1]);
        *reinterpret_cast<__half2*>(g_xg + (size_t)(r0 + rr) * C + j) = h;
    }

    asm volatile("cp.async.wait_group 0;" ::: "memory");
    __syncthreads();
    #pragma unroll
    for (int i = 0; i < 4; i++) {
        int id = tid + i * 512;
        int rr = (id >> 9) + 4, j = (id & 511) * 2;
        unsigned m = (mult * (unsigned)(r0 + rr) + 1u) & 1023u;
        unsigned a0 = ((unsigned)perm[j]     * m) & 1023u;
        unsigned a1 = ((unsigned)perm[j + 1] * m) & 1023u;
        __half2 h = __floats2half2_rn(sx[rr][a0], sx[rr][a1]);
        *reinterpret_cast<__half2*>(g_xg + (size_t)(r0 + rr) * C + j) = h;
    }
}

// ---------------------------------------------------------------------------
// Launch 2: out_g = (xg @ U)/3 + xg, fp16 store.  R7 mainloop; fused epilogue.
// CTA 128x128x64, 256 thr, warps 2(m)x4(n), warp tile 64x32. 2 CTA/SM.
// ---------------------------------------------------------------------------
__device__ __forceinline__ void fill_stage(int f, int tid, uint32_t smb, int by, int bx) {
    const int s = f % STAGES;
    const uint32_t a_base = smb + s * STAGE_BYTES;
    const uint32_t b_base = a_base + A_SM_BYTES;
    const __half* Ag = g_xg + (size_t)(by * BM) * C + f * BK;
    const __half* Bg = g_uh + (size_t)(f * BK) * C + bx * BN;
    #pragma unroll
    for (int i = 0; i < 4; i++) {
        int id = tid + i * 256;
        int r = id >> 3, c = id & 7;
        cp_async16(a_base + r * 128 + ((c ^ (r & 7)) << 4), Ag + (size_t)r * C + c * 8);
    }
    #pragma unroll
    for (int i = 0; i < 4; i++) {
        int id = tid + i * 256;
        int r = id >> 4, c = id & 15;
        cp_async16(b_base + r * 256 + ((c ^ (r & 7)) << 4), Bg + (size_t)r * C + c * 8);
    }
    asm volatile("cp.async.commit_group;" ::: "memory");
}

__global__ void __launch_bounds__(256, 2)
gemm_kernel() {
    extern __shared__ char smem[];
    const uint32_t smb = smem_u32(smem);

    const int bx  = blockIdx.x;       // 0..7
    const int by  = blockIdx.y;       // 0..127
    const int tid = threadIdx.x;
    const int wid = tid >> 5, lane = tid & 31;
    const int wm  = wid & 1;
    const int wn  = wid >> 1;
    const int l7   = lane & 7;
    const int seg1 = (lane >> 3) & 1;
    const int seg2 = lane >> 4;

    float acc[4][4][4];
    #pragma unroll
    for (int i = 0; i < 4; i++)
        #pragma unroll
        for (int j = 0; j < 4; j++)
            #pragma unroll
            for (int q = 0; q < 4; q++) acc[i][j][q] = 0.f;

    #pragma unroll
    for (int f = 0; f < STAGES - 1; f++) fill_stage(f, tid, smb, by, bx);

    const int a_rowloc = wm * 64 + l7 + seg1 * 8;
    const int b_kloc   = l7 + seg1 * 8;
    const int b_ccbase = wn * 4 + seg2;

    for (int kt = 0; kt < NKT; kt++) {
        asm volatile("cp.async.wait_group %0;" :: "n"(STAGES - 2) : "memory");
        __syncthreads();

        const int f = kt + STAGES - 1;
        if (f < NKT) fill_stage(f, tid, smb, by, bx);

        const int s = kt % STAGES;
        const uint32_t As = smb + s * STAGE_BYTES;
        const uint32_t Bs = As + A_SM_BYTES;

        #pragma unroll
        for (int ks = 0; ks < 4; ks++) {
            uint32_t afr[4][4], bfr[2][4];
            const int a_chunk = 2 * ks + seg2;
            #pragma unroll
            for (int mt = 0; mt < 4; mt++)
                ldsm_x4(afr[mt], As + (a_rowloc + mt * 16) * 128 + ((a_chunk ^ l7) << 4));
            const int bk = ks * 16 + b_kloc;
            #pragma unroll
            for (int nb = 0; nb < 2; nb++)
                ldsm_x4_t(bfr[nb], Bs + bk * 256 + (((b_ccbase + nb * 2) ^ l7) << 4));
            #pragma unroll
            for (int mt = 0; mt < 4; mt++)
                #pragma unroll
                for (int nt = 0; nt < 4; nt++)
                    mma_f16(acc[mt][nt], afr[mt],
                            bfr[nt >> 1][2 * (nt & 1)], bfr[nt >> 1][2 * (nt & 1) + 1]);
        }
    }

    // ---- Fused epilogue: reload this CTA's A k-tiles (f = 2bx, 2bx+1) ----
    __syncthreads();                          // all MMA smem reads done
    #pragma unroll
    for (int t = 0; t < 2; t++) {
        const int f = 2 * bx + t;
        const uint32_t a_base = smb + t * STAGE_BYTES;
        const __half* Ag = g_xg + (size_t)(by * BM) * C + f * BK;
        #pragma unroll
        for (int i = 0; i < 4; i++) {
            int id = tid + i * 256;
            int r = id >> 3, c = id & 7;
            cp_async16(a_base + r * 128 + ((c ^ (r & 7)) << 4), Ag + (size_t)r * C + c * 8);
        }
    }
    asm volatile("cp.async.commit_group;" ::: "memory");
    asm volatile("cp.async.wait_group 0;" ::: "memory");
    __syncthreads();

    // out_g = acc/3 + xg   (fp16 store)
    const int qid = lane >> 2, tq = lane & 3;
    #pragma unroll
    for (int mt = 0; mt < 4; mt++) {
        const int rloc0 = wm * 64 + mt * 16 + qid;      // local rows rloc0, rloc0+8
        #pragma unroll
        for (int nt = 0; nt < 4; nt++) {
            const int c   = wn * 32 + nt * 8 + 2 * tq;  // local col (0..127)
            const int t   = c >> 6;                     // which reloaded k-tile
            const int kc  = c & 63;                     // col within tile
            const int chv = kc >> 3;                    // 16B chunk index
            const int wb  = (kc & 7) * 2;               // byte offset in chunk
            #pragma unroll
            for (int h = 0; h < 2; h++) {               // rows rloc0 / rloc0+8
                const int rl = rloc0 + h * 8;
                const char* p = smem + t * STAGE_BYTES + rl * 128
                              + ((chv ^ (rl & 7)) << 4) + wb;
                float2 xv = __half22float2(*reinterpret_cast<const __half2*>(p));
                float ox = fmaf(acc[mt][nt][2 * h],     RAND_SCALE, xv.x);
                float oy = fmaf(acc[mt][nt][2 * h + 1], RAND_SCALE, xv.y);
                *reinterpret_cast<__half2*>(
                    g_og + (size_t)(by * BM + rl) * C + bx * BN + c) =
                    __floats2half2_rn(ox, oy);
            }
        }
    }
}

// ---------------------------------------------------------------------------
// Launch 3: pure permutation.  out[r][a(i)] = float(out_g[r][i])
// 8 rows per 512-thread block; uint4 fp16 reads; 96 MB total traffic.
// ---------------------------------------------------------------------------
__global__ void __launch_bounds__(512)
permute_kernel(const int* __restrict__ perm,
               const int* __restrict__ randint,
               float*     __restrict__ out) {
    __shared__ float so[8][C];
    const int r0 = blockIdx.x * 8;
    const unsigned mult = ((unsigned)randint[0] * 6u) & 1023u;
    const int tid = threadIdx.x;

    // Phase 1: uint4 read of fp16 out_g (8 halves), scattered store into smem
    #pragma unroll
    for (int i = 0; i < 2; i++) {
        int id = tid + i * 512;                  // 0..1023 uint4 chunks
        int rr = id >> 7, j = (id & 127) * 8;
        unsigned m = (mult * (unsigned)(r0 + rr) + 1u) & 1023u;
        uint4 raw = *reinterpret_cast<const uint4*>(g_og + (size_t)(r0 + rr) * C + j);
        const uint32_t w[4] = {raw.x, raw.y, raw.z, raw.w};
        #pragma unroll
        for (int q = 0; q < 4; q++) {
            float2 v = __half22float2(*reinterpret_cast<const __half2*>(&w[q]));
            so[rr][((unsigned)perm[j + 2 * q]     * m) & 1023u] = v.x;
            so[rr][((unsigned)perm[j + 2 * q + 1] * m) & 1023u] = v.y;
        }
    }
    __syncthreads();

    // Phase 2: coalesced float4 write of out
    #pragma unroll
    for (int i = 0; i < 4; i++) {
        int id = tid + i * 512;
        int rr = id >> 8, j = (id & 255) * 4;
        *reinterpret_cast<float4*>(out + (size_t)(r0 + rr) * C + j) =
            *reinterpret_cast<const float4*>(&so[rr][j]);
    }
}

// ---------------------------------------------------------------------------
extern "C" void kernel_launch(void* const* d_in, const int* in_sizes, int n_in,
                              void* d_out, int out_size) {
    const float* x       = (const float*)d_in[0];
    const float* U       = (const float*)d_in[1];
    const int*   perm    = (const int*)d_in[2];
    const int*   randint = (const int*)d_in[3];
    float*       out     = (float*)d_out;

    static bool attr_done = false;
    if (!attr_done) {
        cudaFuncSetAttribute(gemm_kernel,
                             cudaFuncAttributeMaxDynamicSharedMemorySize, GSMEM);
        attr_done = true;
    }

    gather_uconv_kernel<<<GATHER_BLOCKS + UCONV_BLOCKS, 512>>>(x, U, perm, randint);
    gemm_kernel<<<dim3(C / BN, M / BM), 256, GSMEM>>>();
    permute_kernel<<<M / 8, 512>>>(perm, randint, out);
}